// round 3
// baseline (speedup 1.0000x reference)
#include <cuda_runtime.h>

#define LBL 32
#define BMAX 8

// scratch accumulators (zeroed at module load; finalize re-zeros for next replay)
// g_acc1: [B][L][5] = {cnt_k, sum_e0..e3}
// g_acc2: [B][L][2] = {sum_val, cnt}
__device__ float g_acc1[BMAX * LBL * 5];
__device__ float g_acc2[BMAX * LBL * 2];
__device__ unsigned g_done;

// ---------------- Pass 1: kernel-region per-label counts + embedding sums ----
__global__ void __launch_bounds__(256) k_pass1(
    const float* __restrict__ emb, const int* __restrict__ inst,
    const float* __restrict__ ker, const float* __restrict__ tmk,
    int NG, int NPIX)
{
    __shared__ float s[LBL * 5];
    const int b = blockIdx.y;
    for (int i = threadIdx.x; i < LBL * 5; i += blockDim.x) s[i] = 0.f;
    __syncthreads();

    const int4*   ip  = (const int4*)  (inst + (size_t)b * NPIX);
    const float4* kp  = (const float4*)(ker  + (size_t)b * NPIX);
    const float4* mp  = (const float4*)(tmk  + (size_t)b * NPIX);
    const float*  ep  = emb + (size_t)b * 4 * NPIX;
    const float4* e0p = (const float4*)(ep);
    const float4* e1p = (const float4*)(ep + NPIX);
    const float4* e2p = (const float4*)(ep + 2 * NPIX);
    const float4* e3p = (const float4*)(ep + 3 * NPIX);

    const int stride = gridDim.x * blockDim.x;
    for (int g = blockIdx.x * blockDim.x + threadIdx.x; g < NG; g += stride) {
        int4   lb = ip[g];
        float4 kv = kp[g];
        float4 mv = mp[g];
        int l0 = (fminf(kv.x, mv.x) > 0.5f) ? lb.x : 0;
        int l1 = (fminf(kv.y, mv.y) > 0.5f) ? lb.y : 0;
        int l2 = (fminf(kv.z, mv.z) > 0.5f) ? lb.z : 0;
        int l3 = (fminf(kv.w, mv.w) > 0.5f) ? lb.w : 0;
        if ((l0 | l1 | l2 | l3) != 0) {
            float4 e0 = e0p[g], e1 = e1p[g], e2 = e2p[g], e3 = e3p[g];
            if (l0) { float* sp = s + l0 * 5; atomicAdd(sp, 1.f); atomicAdd(sp+1, e0.x); atomicAdd(sp+2, e1.x); atomicAdd(sp+3, e2.x); atomicAdd(sp+4, e3.x); }
            if (l1) { float* sp = s + l1 * 5; atomicAdd(sp, 1.f); atomicAdd(sp+1, e0.y); atomicAdd(sp+2, e1.y); atomicAdd(sp+3, e2.y); atomicAdd(sp+4, e3.y); }
            if (l2) { float* sp = s + l2 * 5; atomicAdd(sp, 1.f); atomicAdd(sp+1, e0.z); atomicAdd(sp+2, e1.z); atomicAdd(sp+3, e2.z); atomicAdd(sp+4, e3.z); }
            if (l3) { float* sp = s + l3 * 5; atomicAdd(sp, 1.f); atomicAdd(sp+1, e0.w); atomicAdd(sp+2, e1.w); atomicAdd(sp+3, e2.w); atomicAdd(sp+4, e3.w); }
        }
    }
    // scalar tail (NPIX % 4), handled by block x==0 only
    int rem = NPIX & 3;
    if (rem && blockIdx.x == 0 && threadIdx.x < rem) {
        int i = NG * 4 + threadIdx.x;
        const int*   ips = inst + (size_t)b * NPIX;
        const float* kps = ker  + (size_t)b * NPIX;
        const float* mps = tmk  + (size_t)b * NPIX;
        int l = (fminf(kps[i], mps[i]) > 0.5f) ? ips[i] : 0;
        if (l) {
            float* sp = s + l * 5;
            atomicAdd(sp, 1.f);
            atomicAdd(sp+1, ep[i]); atomicAdd(sp+2, ep[i+NPIX]);
            atomicAdd(sp+3, ep[i+2*NPIX]); atomicAdd(sp+4, ep[i+3*NPIX]);
        }
    }
    __syncthreads();

    for (int i = threadIdx.x + 5; i < LBL * 5; i += blockDim.x)  // skip label 0
        if (s[i] != 0.f) atomicAdd(&g_acc1[b * LBL * 5 + i], s[i]);
}

// ---------------- Pass 2 + fused finalize --------------------------------
__global__ void __launch_bounds__(256) k_pass2(
    const float* __restrict__ emb, const int* __restrict__ inst,
    const float* __restrict__ tmk, float* __restrict__ out,
    int NG, int NPIX, int B)
{
    __shared__ float4 meanv[LBL];
    __shared__ float s[LBL * 2];
    __shared__ int isLast;
    const int b = blockIdx.y;

    if (threadIdx.x < LBL) {
        int l = threadIdx.x;
        const float* a = &g_acc1[(b * LBL + l) * 5];
        float inv = 1.f / fmaxf(a[0], 1.f);
        meanv[l] = (l == 0) ? make_float4(0.f, 0.f, 0.f, 0.f)
                            : make_float4(a[1]*inv, a[2]*inv, a[3]*inv, a[4]*inv);
    }
    for (int i = threadIdx.x; i < LBL * 2; i += blockDim.x) s[i] = 0.f;
    __syncthreads();

    const int4*   ip  = (const int4*)  (inst + (size_t)b * NPIX);
    const float4* mp  = (const float4*)(tmk  + (size_t)b * NPIX);
    const float*  ep  = emb + (size_t)b * 4 * NPIX;
    const float4* e0p = (const float4*)(ep);
    const float4* e1p = (const float4*)(ep + NPIX);
    const float4* e2p = (const float4*)(ep + 2 * NPIX);
    const float4* e3p = (const float4*)(ep + 3 * NPIX);

    const int stride = gridDim.x * blockDim.x;
    for (int g = blockIdx.x * blockDim.x + threadIdx.x; g < NG; g += stride) {
        int4   lb = ip[g];
        float4 mv = mp[g];
        int l0 = (mv.x > 0.5f) ? lb.x : 0;
        int l1 = (mv.y > 0.5f) ? lb.y : 0;
        int l2 = (mv.z > 0.5f) ? lb.z : 0;
        int l3 = (mv.w > 0.5f) ? lb.w : 0;
        if ((l0 | l1 | l2 | l3) != 0) {
            float4 e0 = e0p[g], e1 = e1p[g], e2 = e2p[g], e3 = e3p[g];
            #define PAN_PIX(L, X)                                              \
                if (L) {                                                       \
                    float4 m = meanv[L];                                       \
                    float d0 = e0.X - m.x, d1 = e1.X - m.y;                    \
                    float d2 = e2.X - m.z, d3 = e3.X - m.w;                    \
                    float sq = fmaf(d0,d0, fmaf(d1,d1, fmaf(d2,d2, d3*d3)));   \
                    float dist = (sq > 0.f) ? sq * rsqrtf(sq) : 0.f;           \
                    float r = fmaxf(dist - 0.5f, 0.f);                         \
                    float val = __logf(fmaf(r, r, 1.f));                       \
                    atomicAdd(&s[L * 2 + 0], val);                             \
                    atomicAdd(&s[L * 2 + 1], 1.f);                             \
                }
            PAN_PIX(l0, x) PAN_PIX(l1, y) PAN_PIX(l2, z) PAN_PIX(l3, w)
            #undef PAN_PIX
        }
    }
    int rem = NPIX & 3;
    if (rem && blockIdx.x == 0 && threadIdx.x < rem) {
        int i = NG * 4 + threadIdx.x;
        const int*   ips = inst + (size_t)b * NPIX;
        const float* mps = tmk  + (size_t)b * NPIX;
        int l = (mps[i] > 0.5f) ? ips[i] : 0;
        if (l) {
            float4 m = meanv[l];
            float d0 = ep[i] - m.x, d1 = ep[i+NPIX] - m.y;
            float d2 = ep[i+2*NPIX] - m.z, d3 = ep[i+3*NPIX] - m.w;
            float sq = fmaf(d0,d0, fmaf(d1,d1, fmaf(d2,d2, d3*d3)));
            float dist = (sq > 0.f) ? sq * rsqrtf(sq) : 0.f;
            float r = fmaxf(dist - 0.5f, 0.f);
            atomicAdd(&s[l*2+0], __logf(fmaf(r, r, 1.f)));
            atomicAdd(&s[l*2+1], 1.f);
        }
    }
    __syncthreads();

    for (int i = threadIdx.x + 2; i < LBL * 2; i += blockDim.x)  // skip label 0
        if (s[i] != 0.f) atomicAdd(&g_acc2[b * LBL * 2 + i], s[i]);
    __threadfence();
    if (threadIdx.x == 0) {
        unsigned total = gridDim.x * gridDim.y;
        isLast = (atomicAdd(&g_done, 1u) == total - 1u);
    }
    __syncthreads();
    if (!isLast) return;

    // ---------- finalize: warp w handles batch w ----------
    __threadfence();
    __shared__ float fm[BMAX][LBL][4];
    const int w = threadIdx.x >> 5;
    const int l = threadIdx.x & 31;

    if (w < B) {
        const float* a = &g_acc1[(w * LBL + l) * 5];
        float c = a[0];                       // 0 for l==0 (not accumulated)
        float m0 = 0.f, m1 = 0.f, m2 = 0.f, m3 = 0.f;
        if (l > 0) {
            float inv = 1.f / fmaxf(c, 1.f);
            m0 = a[1]*inv; m1 = a[2]*inv; m2 = a[3]*inv; m3 = a[4]*inv;
        }
        // recover label-0 count: NPIX - sum of active counts
        float csum = (l > 0) ? c : 0.f;
        for (int o = 16; o; o >>= 1) csum += __shfl_xor_sync(0xffffffffu, csum, o);
        if (l == 0) c = (float)NPIX - csum;

        bool present = (c > 0.f);
        unsigned pb = __ballot_sync(0xffffffffu, present);
        int ni = __popc(pb);
        unsigned nzb = pb & ~1u;
        bool nz = present && (l > 0);

        fm[w][l][0] = m0; fm[w][l][1] = m1; fm[w][l][2] = m2; fm[w][l][3] = m3;
        __syncwarp();

        float sv = g_acc2[(w * LBL + l) * 2 + 0];
        float ct = g_acc2[(w * LBL + l) * 2 + 1];
        float aggl = nz ? sv / fmaxf(ct, 1.f) : 0.f;

        float sq = m0*m0 + m1*m1 + m2*m2 + m3*m3;
        float nrm = (sq > 0.f) ? sqrtf(sq) : 0.f;
        float reg = present ? log1pf(nrm) : 0.f;

        float ds = 0.f, dc = 0.f;
        if (nz) {
            #pragma unroll
            for (int j = 1; j < LBL; j++) {
                if (j != l && ((nzb >> j) & 1u)) {
                    float p0 = m0 - fm[w][j][0];
                    float p1 = m1 - fm[w][j][1];
                    float p2 = m2 - fm[w][j][2];
                    float p3 = m3 - fm[w][j][3];
                    float psq = p0*p0 + p1*p1 + p2*p2 + p3*p3;
                    float pd = (psq > 0.f) ? sqrtf(psq) : 0.f;
                    float r = fmaxf(3.0f - pd, 0.f);     // 2*DELTA_DIS
                    ds += log1pf(r * r);
                    dc += 1.f;
                }
            }
        }
        for (int o = 16; o; o >>= 1) {
            aggl += __shfl_down_sync(0xffffffffu, aggl, o);
            reg  += __shfl_down_sync(0xffffffffu, reg,  o);
            ds   += __shfl_down_sync(0xffffffffu, ds,   o);
            dc   += __shfl_down_sync(0xffffffffu, dc,   o);
        }
        if (l == 0) {
            float l_agg = aggl / (float)((ni - 1) > 1 ? (ni - 1) : 1);
            float l_reg = reg / (float)(ni > 1 ? ni : 1) * 0.001f;
            float l_dis = (ni > 2) ? ds / fmaxf(dc, 1.f) : 0.f;
            out[w] = (ni <= 1) ? 0.f : (l_agg + l_dis + l_reg);
        }
    }
    __syncthreads();     // all reads of g_acc done — now reset for next replay
    for (int i = threadIdx.x; i < BMAX * LBL * 5; i += blockDim.x) g_acc1[i] = 0.f;
    for (int i = threadIdx.x; i < BMAX * LBL * 2; i += blockDim.x) g_acc2[i] = 0.f;
    if (threadIdx.x == 0) g_done = 0u;
}

extern "C" void kernel_launch(void* const* d_in, const int* in_sizes, int n_in,
                              void* d_out, int out_size) {
    const float* emb  = (const float*)d_in[0];
    const int*   inst = (const int*)  d_in[1];
    const float* ker  = (const float*)d_in[2];
    const float* tmk  = (const float*)d_in[3];
    float* out = (float*)d_out;

    int B = out_size;
    if (B > BMAX) B = BMAX;
    int NPIX = in_sizes[1] / B;
    int NG = NPIX >> 2;

    dim3 grid(148, B);
    k_pass1<<<grid, 256>>>(emb, inst, ker, tmk, NG, NPIX);
    k_pass2<<<grid, 256>>>(emb, inst, tmk, out, NG, NPIX, B);
}

// round 4
// speedup vs baseline: 1.1878x; 1.1878x over previous
#include <cuda_runtime.h>

#define LBL 32
#define BMAX 8
typedef unsigned long long ull;
typedef long long ll;

#define S_EMB 65536.f          // 2^16 fixed-point scale for embedding sums
#define INV_S_EMB (1.f/65536.f)
#define S_VAL 262144.f         // 2^18 scale for log-val sums
#define INV_S_VAL (1.f/262144.f)

// scratch (zeroed at load; finalize re-zeros for next graph replay)
__device__ ull g_s01[BMAX * LBL];   // packed (sum_e0, sum_e1)
__device__ ull g_s23[BMAX * LBL];   // packed (sum_e2, sum_e3)
__device__ int g_cnt1[BMAX * LBL];  // kernel-region counts
__device__ ull g_p2[BMAX * LBL];    // packed (sum_val<<22) + cnt
__device__ unsigned g_done;

__device__ __forceinline__ ull pack2(float a, float b) {
    int ia = __float2int_rn(a * S_EMB);
    int ib = __float2int_rn(b * S_EMB);
    return (ull)(((ll)ib << 32) + (ll)ia);
}
__device__ __forceinline__ void unpack2(ull p, float& a, float& b) {
    ll P = (ll)p;
    int ia = (int)(unsigned)(P & 0xFFFFFFFFll);
    int ib = (int)((P - (ll)ia) >> 32);
    a = (float)ia * INV_S_EMB;
    b = (float)ib * INV_S_EMB;
}

// ---------------- Pass 1: kernel-region per-label counts + embedding sums ----
__global__ void __launch_bounds__(256) k_pass1(
    const float* __restrict__ emb, const int* __restrict__ inst,
    const float* __restrict__ ker, const float* __restrict__ tmk,
    int NG, int NPIX)
{
    __shared__ ull s01[LBL], s23[LBL];
    __shared__ int scnt[LBL];
    const int b = blockIdx.y;
    if (threadIdx.x < LBL) { s01[threadIdx.x] = 0ull; s23[threadIdx.x] = 0ull; scnt[threadIdx.x] = 0; }
    __syncthreads();

    const int4*   ip  = (const int4*)  (inst + (size_t)b * NPIX);
    const float4* kp  = (const float4*)(ker  + (size_t)b * NPIX);
    const float4* mp  = (const float4*)(tmk  + (size_t)b * NPIX);
    const float*  ep  = emb + (size_t)b * 4 * NPIX;
    const float4* e0p = (const float4*)(ep);
    const float4* e1p = (const float4*)(ep + NPIX);
    const float4* e2p = (const float4*)(ep + 2 * NPIX);
    const float4* e3p = (const float4*)(ep + 3 * NPIX);

    const int stride = gridDim.x * blockDim.x;
    for (int g = blockIdx.x * blockDim.x + threadIdx.x; g < NG; g += stride) {
        int4   lb = ip[g];
        float4 kv = kp[g];
        float4 mv = mp[g];
        int l0 = (fminf(kv.x, mv.x) > 0.5f) ? lb.x : 0;
        int l1 = (fminf(kv.y, mv.y) > 0.5f) ? lb.y : 0;
        int l2 = (fminf(kv.z, mv.z) > 0.5f) ? lb.z : 0;
        int l3 = (fminf(kv.w, mv.w) > 0.5f) ? lb.w : 0;
        if ((l0 | l1 | l2 | l3) != 0) {
            float4 e0 = e0p[g], e1 = e1p[g], e2 = e2p[g], e3 = e3p[g];
            if (l0) { atomicAdd(&s01[l0], pack2(e0.x, e1.x)); atomicAdd(&s23[l0], pack2(e2.x, e3.x)); atomicAdd(&scnt[l0], 1); }
            if (l1) { atomicAdd(&s01[l1], pack2(e0.y, e1.y)); atomicAdd(&s23[l1], pack2(e2.y, e3.y)); atomicAdd(&scnt[l1], 1); }
            if (l2) { atomicAdd(&s01[l2], pack2(e0.z, e1.z)); atomicAdd(&s23[l2], pack2(e2.z, e3.z)); atomicAdd(&scnt[l2], 1); }
            if (l3) { atomicAdd(&s01[l3], pack2(e0.w, e1.w)); atomicAdd(&s23[l3], pack2(e2.w, e3.w)); atomicAdd(&scnt[l3], 1); }
        }
    }
    // scalar tail (unused when NPIX%4==0)
    int rem = NPIX & 3;
    if (rem && blockIdx.x == 0 && threadIdx.x < rem) {
        int i = NG * 4 + threadIdx.x;
        const int*   ips = inst + (size_t)b * NPIX;
        const float* kps = ker  + (size_t)b * NPIX;
        const float* mps = tmk  + (size_t)b * NPIX;
        int l = (fminf(kps[i], mps[i]) > 0.5f) ? ips[i] : 0;
        if (l) {
            atomicAdd(&s01[l], pack2(ep[i], ep[i + NPIX]));
            atomicAdd(&s23[l], pack2(ep[i + 2 * NPIX], ep[i + 3 * NPIX]));
            atomicAdd(&scnt[l], 1);
        }
    }
    __syncthreads();

    if (threadIdx.x >= 1 && threadIdx.x < LBL) {   // skip label 0
        int l = threadIdx.x;
        if (scnt[l]) {
            atomicAdd(&g_s01[b * LBL + l], s01[l]);
            atomicAdd(&g_s23[b * LBL + l], s23[l]);
            atomicAdd(&g_cnt1[b * LBL + l], scnt[l]);
        }
    }
}

// ---------------- Pass 2 + fused finalize --------------------------------
__global__ void __launch_bounds__(256) k_pass2(
    const float* __restrict__ emb, const int* __restrict__ inst,
    const float* __restrict__ tmk, float* __restrict__ out,
    int NG, int NPIX, int B)
{
    __shared__ float4 meanv[LBL];
    __shared__ ull sp2[LBL];
    __shared__ int isLast;
    const int b = blockIdx.y;

    if (threadIdx.x < LBL) {
        int l = threadIdx.x;
        float m0 = 0.f, m1 = 0.f, m2 = 0.f, m3 = 0.f;
        if (l > 0) {
            float inv = 1.f / fmaxf((float)g_cnt1[b * LBL + l], 1.f);
            float a0, a1, a2, a3;
            unpack2(g_s01[b * LBL + l], a0, a1);
            unpack2(g_s23[b * LBL + l], a2, a3);
            m0 = a0 * inv; m1 = a1 * inv; m2 = a2 * inv; m3 = a3 * inv;
        }
        meanv[l] = make_float4(m0, m1, m2, m3);
        sp2[l] = 0ull;
    }
    __syncthreads();

    const int4*   ip  = (const int4*)  (inst + (size_t)b * NPIX);
    const float4* mp  = (const float4*)(tmk  + (size_t)b * NPIX);
    const float*  ep  = emb + (size_t)b * 4 * NPIX;
    const float4* e0p = (const float4*)(ep);
    const float4* e1p = (const float4*)(ep + NPIX);
    const float4* e2p = (const float4*)(ep + 2 * NPIX);
    const float4* e3p = (const float4*)(ep + 3 * NPIX);

    const int stride = gridDim.x * blockDim.x;
    for (int g = blockIdx.x * blockDim.x + threadIdx.x; g < NG; g += stride) {
        int4   lb = ip[g];
        float4 mv = mp[g];
        int l0 = (mv.x > 0.5f) ? lb.x : 0;
        int l1 = (mv.y > 0.5f) ? lb.y : 0;
        int l2 = (mv.z > 0.5f) ? lb.z : 0;
        int l3 = (mv.w > 0.5f) ? lb.w : 0;
        if ((l0 | l1 | l2 | l3) != 0) {
            float4 e0 = e0p[g], e1 = e1p[g], e2 = e2p[g], e3 = e3p[g];
            #define PAN_PIX(L, X)                                              \
                if (L) {                                                       \
                    float4 m = meanv[L];                                       \
                    float d0 = e0.X - m.x, d1 = e1.X - m.y;                    \
                    float d2 = e2.X - m.z, d3 = e3.X - m.w;                    \
                    float sq = fmaf(d0,d0, fmaf(d1,d1, fmaf(d2,d2, d3*d3)));   \
                    float dist = (sq > 0.f) ? sq * rsqrtf(sq) : 0.f;           \
                    float r = fmaxf(dist - 0.5f, 0.f);                         \
                    float val = __logf(fmaf(r, r, 1.f));                       \
                    unsigned vf = (unsigned)__float2int_rn(val * S_VAL);       \
                    atomicAdd(&sp2[L], ((ull)vf << 22) + 1ull);                \
                }
            PAN_PIX(l0, x) PAN_PIX(l1, y) PAN_PIX(l2, z) PAN_PIX(l3, w)
            #undef PAN_PIX
        }
    }
    int rem = NPIX & 3;
    if (rem && blockIdx.x == 0 && threadIdx.x < rem) {
        int i = NG * 4 + threadIdx.x;
        const int*   ips = inst + (size_t)b * NPIX;
        const float* mps = tmk  + (size_t)b * NPIX;
        int l = (mps[i] > 0.5f) ? ips[i] : 0;
        if (l) {
            float4 m = meanv[l];
            float d0 = ep[i] - m.x, d1 = ep[i+NPIX] - m.y;
            float d2 = ep[i+2*NPIX] - m.z, d3 = ep[i+3*NPIX] - m.w;
            float sq = fmaf(d0,d0, fmaf(d1,d1, fmaf(d2,d2, d3*d3)));
            float dist = (sq > 0.f) ? sq * rsqrtf(sq) : 0.f;
            float r = fmaxf(dist - 0.5f, 0.f);
            unsigned vf = (unsigned)__float2int_rn(__logf(fmaf(r, r, 1.f)) * S_VAL);
            atomicAdd(&sp2[l], ((ull)vf << 22) + 1ull);
        }
    }
    __syncthreads();

    if (threadIdx.x >= 1 && threadIdx.x < LBL) {   // skip label 0
        int l = threadIdx.x;
        if (sp2[l]) atomicAdd(&g_p2[b * LBL + l], sp2[l]);
    }
    __threadfence();
    if (threadIdx.x == 0) {
        unsigned total = gridDim.x * gridDim.y;
        isLast = (atomicAdd(&g_done, 1u) == total - 1u);
    }
    __syncthreads();
    if (!isLast) return;

    // ---------- finalize: warp w handles batch w ----------
    __threadfence();
    __shared__ float fm[BMAX][LBL][4];
    const int w = threadIdx.x >> 5;
    const int l = threadIdx.x & 31;

    if (w < B) {
        int   ci = g_cnt1[w * LBL + l];           // 0 for l==0 (never accumulated)
        float c  = (float)ci;
        float m0 = 0.f, m1 = 0.f, m2 = 0.f, m3 = 0.f;
        if (l > 0 && ci > 0) {
            float inv = 1.f / c;
            float a0, a1, a2, a3;
            unpack2(g_s01[w * LBL + l], a0, a1);
            unpack2(g_s23[w * LBL + l], a2, a3);
            m0 = a0 * inv; m1 = a1 * inv; m2 = a2 * inv; m3 = a3 * inv;
        }
        // recover label-0 count: NPIX - sum of active counts
        float csum = (l > 0) ? c : 0.f;
        for (int o = 16; o; o >>= 1) csum += __shfl_xor_sync(0xffffffffu, csum, o);
        if (l == 0) c = (float)NPIX - csum;

        bool present = (c > 0.f);
        unsigned pb = __ballot_sync(0xffffffffu, present);
        int ni = __popc(pb);
        unsigned nzb = pb & ~1u;
        bool nz = present && (l > 0);

        fm[w][l][0] = m0; fm[w][l][1] = m1; fm[w][l][2] = m2; fm[w][l][3] = m3;
        __syncwarp();

        // aggregation term
        ull p2 = g_p2[w * LBL + l];
        float sv = (float)(double)(p2 >> 22) * INV_S_VAL;
        float ct = (float)(unsigned)(p2 & 0x3FFFFFull);
        float aggl = nz ? sv / fmaxf(ct, 1.f) : 0.f;

        // regularizer
        float sq = m0*m0 + m1*m1 + m2*m2 + m3*m3;
        float nrm = (sq > 0.f) ? sqrtf(sq) : 0.f;
        float reg = present ? log1pf(nrm) : 0.f;

        // discrimination
        float ds = 0.f, dc = 0.f;
        if (nz) {
            #pragma unroll
            for (int j = 1; j < LBL; j++) {
                if (j != l && ((nzb >> j) & 1u)) {
                    float p0 = m0 - fm[w][j][0];
                    float p1 = m1 - fm[w][j][1];
                    float p2f = m2 - fm[w][j][2];
                    float p3 = m3 - fm[w][j][3];
                    float psq = p0*p0 + p1*p1 + p2f*p2f + p3*p3;
                    float pd = (psq > 0.f) ? sqrtf(psq) : 0.f;
                    float r = fmaxf(3.0f - pd, 0.f);     // 2*DELTA_DIS
                    ds += log1pf(r * r);
                    dc += 1.f;
                }
            }
        }
        for (int o = 16; o; o >>= 1) {
            aggl += __shfl_down_sync(0xffffffffu, aggl, o);
            reg  += __shfl_down_sync(0xffffffffu, reg,  o);
            ds   += __shfl_down_sync(0xffffffffu, ds,   o);
            dc   += __shfl_down_sync(0xffffffffu, dc,   o);
        }
        if (l == 0) {
            float l_agg = aggl / (float)((ni - 1) > 1 ? (ni - 1) : 1);
            float l_reg = reg / (float)(ni > 1 ? ni : 1) * 0.001f;
            float l_dis = (ni > 2) ? ds / fmaxf(dc, 1.f) : 0.f;
            out[w] = (ni <= 1) ? 0.f : (l_agg + l_dis + l_reg);
        }
    }
    __syncthreads();     // all reads done — reset scratch for next replay
    if (threadIdx.x < BMAX * LBL) {
        g_s01[threadIdx.x] = 0ull;
        g_s23[threadIdx.x] = 0ull;
        g_cnt1[threadIdx.x] = 0;
        g_p2[threadIdx.x]  = 0ull;
    }
    if (threadIdx.x == 0) g_done = 0u;
}

extern "C" void kernel_launch(void* const* d_in, const int* in_sizes, int n_in,
                              void* d_out, int out_size) {
    const float* emb  = (const float*)d_in[0];
    const int*   inst = (const int*)  d_in[1];
    const float* ker  = (const float*)d_in[2];
    const float* tmk  = (const float*)d_in[3];
    float* out = (float*)d_out;

    int B = out_size;
    if (B > BMAX) B = BMAX;
    int NPIX = in_sizes[1] / B;
    int NG = NPIX >> 2;

    dim3 grid(296, B);
    k_pass1<<<grid, 256>>>(emb, inst, ker, tmk, NG, NPIX);
    k_pass2<<<grid, 256>>>(emb, inst, tmk, out, NG, NPIX, B);
}

// round 5
// speedup vs baseline: 1.2555x; 1.0570x over previous
#include <cuda_runtime.h>

#define LBL 32
#define BMAX 8
#define CPB 74           // chunks (blocks) per batch -> grid = B*CPB = 592 = 148*4
typedef unsigned long long ull;
typedef long long ll;

#define S_EMB 65536.f          // 2^16 fixed-point scale for embedding sums
#define INV_S_EMB (1.f/65536.f)
#define S_VAL 262144.f         // 2^18 scale for log-val sums
#define INV_S_VAL (1.f/262144.f)

// scratch (zeroed at module load; finalize re-zeros for next graph replay)
__device__ ull g_s01[BMAX * LBL];   // packed (sum_e0, sum_e1)
__device__ ull g_s23[BMAX * LBL];   // packed (sum_e2, sum_e3)
__device__ int g_cnt1[BMAX * LBL];  // kernel-region counts
__device__ ull g_p2[BMAX * LBL];    // packed (sum_val<<22) + cnt
__device__ unsigned g_bar1, g_bar2;

__device__ __forceinline__ ull pack2(float a, float b) {
    int ia = __float2int_rn(a * S_EMB);
    int ib = __float2int_rn(b * S_EMB);
    return (ull)(((ll)ib << 32) + (ll)ia);
}
__device__ __forceinline__ void unpack2(ull p, float& a, float& b) {
    ll P = (ll)p;
    int ia = (int)(unsigned)(P & 0xFFFFFFFFll);
    int ib = (int)((P - (ll)ia) >> 32);
    a = (float)ia * INV_S_EMB;
    b = (float)ib * INV_S_EMB;
}

__global__ void __launch_bounds__(256, 6) k_fused(
    const float* __restrict__ emb, const int* __restrict__ inst,
    const float* __restrict__ ker, const float* __restrict__ tmk,
    float* __restrict__ out, int NG, int NPIX, int B)
{
    const int tid   = threadIdx.x;
    const int b     = blockIdx.x % B;
    const int chunk = blockIdx.x / B;
    const int CS    = (NG + CPB - 1) / CPB;
    const int gBeg  = chunk * CS;
    const int gEnd  = (gBeg + CS < NG) ? gBeg + CS : NG;

    __shared__ ull s01[LBL], s23[LBL], sp2[LBL];
    __shared__ int scnt[LBL];
    __shared__ float4 meanv[LBL];
    __shared__ int isLast;

    if (tid < LBL) { s01[tid] = 0ull; s23[tid] = 0ull; sp2[tid] = 0ull; scnt[tid] = 0; }
    __syncthreads();

    const int4*   ip  = (const int4*)  (inst + (size_t)b * NPIX);
    const float4* kp  = (const float4*)(ker  + (size_t)b * NPIX);
    const float4* mp  = (const float4*)(tmk  + (size_t)b * NPIX);
    const float*  ep  = emb + (size_t)b * 4 * NPIX;
    const float4* e0p = (const float4*)(ep);
    const float4* e1p = (const float4*)(ep + NPIX);
    const float4* e2p = (const float4*)(ep + 2 * NPIX);
    const float4* e3p = (const float4*)(ep + 3 * NPIX);

    // ---------------- pass 1: kernel-region per-label counts + sums ----------
    for (int g = gBeg + tid; g < gEnd; g += 256) {
        int4   lb = ip[g];
        float4 kv = kp[g];
        float4 mv = mp[g];
        int l0 = (fminf(kv.x, mv.x) > 0.5f) ? lb.x : 0;
        int l1 = (fminf(kv.y, mv.y) > 0.5f) ? lb.y : 0;
        int l2 = (fminf(kv.z, mv.z) > 0.5f) ? lb.z : 0;
        int l3 = (fminf(kv.w, mv.w) > 0.5f) ? lb.w : 0;
        if ((l0 | l1 | l2 | l3) != 0) {
            float4 e0 = e0p[g], e1 = e1p[g], e2 = e2p[g], e3 = e3p[g];
            if (l0) { atomicAdd(&s01[l0], pack2(e0.x, e1.x)); atomicAdd(&s23[l0], pack2(e2.x, e3.x)); atomicAdd(&scnt[l0], 1); }
            if (l1) { atomicAdd(&s01[l1], pack2(e0.y, e1.y)); atomicAdd(&s23[l1], pack2(e2.y, e3.y)); atomicAdd(&scnt[l1], 1); }
            if (l2) { atomicAdd(&s01[l2], pack2(e0.z, e1.z)); atomicAdd(&s23[l2], pack2(e2.z, e3.z)); atomicAdd(&scnt[l2], 1); }
            if (l3) { atomicAdd(&s01[l3], pack2(e0.w, e1.w)); atomicAdd(&s23[l3], pack2(e2.w, e3.w)); atomicAdd(&scnt[l3], 1); }
        }
    }
    int rem = NPIX & 3;
    if (rem && chunk == 0 && tid < rem) {
        int i = NG * 4 + tid;
        const int*   ips = inst + (size_t)b * NPIX;
        const float* kps = ker  + (size_t)b * NPIX;
        const float* mps = tmk  + (size_t)b * NPIX;
        int l = (fminf(kps[i], mps[i]) > 0.5f) ? ips[i] : 0;
        if (l) {
            atomicAdd(&s01[l], pack2(ep[i], ep[i + NPIX]));
            atomicAdd(&s23[l], pack2(ep[i + 2 * NPIX], ep[i + 3 * NPIX]));
            atomicAdd(&scnt[l], 1);
        }
    }
    __syncthreads();
    if (tid >= 1 && tid < LBL && scnt[tid]) {
        atomicAdd(&g_s01[b * LBL + tid], s01[tid]);
        atomicAdd(&g_s23[b * LBL + tid], s23[tid]);
        atomicAdd(&g_cnt1[b * LBL + tid], scnt[tid]);
    }
    __threadfence();
    __syncthreads();

    // ---------------- device-wide barrier (all blocks resident by construction)
    if (tid == 0) {
        atomicAdd(&g_bar1, 1u);
        while (atomicAdd(&g_bar1, 0u) < (unsigned)gridDim.x) {}
    }
    __syncthreads();
    __threadfence();

    // ---------------- pass 2: distances to per-label means --------------------
    if (tid < LBL) {
        float m0 = 0.f, m1 = 0.f, m2 = 0.f, m3 = 0.f;
        if (tid > 0) {
            float inv = 1.f / fmaxf((float)g_cnt1[b * LBL + tid], 1.f);
            float a0, a1, a2, a3;
            unpack2(g_s01[b * LBL + tid], a0, a1);
            unpack2(g_s23[b * LBL + tid], a2, a3);
            m0 = a0 * inv; m1 = a1 * inv; m2 = a2 * inv; m3 = a3 * inv;
        }
        meanv[tid] = make_float4(m0, m1, m2, m3);
    }
    __syncthreads();

    for (int g = gBeg + tid; g < gEnd; g += 256) {
        int4   lb = ip[g];
        float4 mv = mp[g];
        int l0 = (mv.x > 0.5f) ? lb.x : 0;
        int l1 = (mv.y > 0.5f) ? lb.y : 0;
        int l2 = (mv.z > 0.5f) ? lb.z : 0;
        int l3 = (mv.w > 0.5f) ? lb.w : 0;
        if ((l0 | l1 | l2 | l3) != 0) {
            float4 e0 = e0p[g], e1 = e1p[g], e2 = e2p[g], e3 = e3p[g];
            #define PAN_PIX(L, X)                                              \
                if (L) {                                                       \
                    float4 m = meanv[L];                                       \
                    float d0 = e0.X - m.x, d1 = e1.X - m.y;                    \
                    float d2 = e2.X - m.z, d3 = e3.X - m.w;                    \
                    float sq = fmaf(d0,d0, fmaf(d1,d1, fmaf(d2,d2, d3*d3)));   \
                    float dist = (sq > 0.f) ? sq * rsqrtf(sq) : 0.f;           \
                    float r = fmaxf(dist - 0.5f, 0.f);                         \
                    float val = __logf(fmaf(r, r, 1.f));                       \
                    unsigned vf = (unsigned)__float2int_rn(val * S_VAL);       \
                    atomicAdd(&sp2[L], ((ull)vf << 22) + 1ull);                \
                }
            PAN_PIX(l0, x) PAN_PIX(l1, y) PAN_PIX(l2, z) PAN_PIX(l3, w)
            #undef PAN_PIX
        }
    }
    if (rem && chunk == 0 && tid < rem) {
        int i = NG * 4 + tid;
        const int*   ips = inst + (size_t)b * NPIX;
        const float* mps = tmk  + (size_t)b * NPIX;
        int l = (mps[i] > 0.5f) ? ips[i] : 0;
        if (l) {
            float4 m = meanv[l];
            float d0 = ep[i] - m.x, d1 = ep[i+NPIX] - m.y;
            float d2 = ep[i+2*NPIX] - m.z, d3 = ep[i+3*NPIX] - m.w;
            float sq = fmaf(d0,d0, fmaf(d1,d1, fmaf(d2,d2, d3*d3)));
            float dist = (sq > 0.f) ? sq * rsqrtf(sq) : 0.f;
            float r = fmaxf(dist - 0.5f, 0.f);
            unsigned vf = (unsigned)__float2int_rn(__logf(fmaf(r, r, 1.f)) * S_VAL);
            atomicAdd(&sp2[l], ((ull)vf << 22) + 1ull);
        }
    }
    __syncthreads();
    if (tid >= 1 && tid < LBL && sp2[tid]) atomicAdd(&g_p2[b * LBL + tid], sp2[tid]);
    __threadfence();
    __syncthreads();
    if (tid == 0)
        isLast = (atomicAdd(&g_bar2, 1u) == (unsigned)gridDim.x - 1u);
    __syncthreads();
    if (!isLast) return;

    // ---------------- finalize: warp w handles batch w -------------------------
    __threadfence();
    __shared__ float fm[BMAX][LBL][4];
    const int w = tid >> 5;
    const int l = tid & 31;

    if (w < B) {
        int   ci = g_cnt1[w * LBL + l];           // 0 for l==0 (never accumulated)
        float c  = (float)ci;
        float m0 = 0.f, m1 = 0.f, m2 = 0.f, m3 = 0.f;
        if (l > 0 && ci > 0) {
            float inv = 1.f / c;
            float a0, a1, a2, a3;
            unpack2(g_s01[w * LBL + l], a0, a1);
            unpack2(g_s23[w * LBL + l], a2, a3);
            m0 = a0 * inv; m1 = a1 * inv; m2 = a2 * inv; m3 = a3 * inv;
        }
        // recover label-0 count: NPIX - sum of active counts
        float csum = (l > 0) ? c : 0.f;
        for (int o = 16; o; o >>= 1) csum += __shfl_xor_sync(0xffffffffu, csum, o);
        if (l == 0) c = (float)NPIX - csum;

        bool present = (c > 0.f);
        unsigned pb = __ballot_sync(0xffffffffu, present);
        int ni = __popc(pb);
        unsigned nzb = pb & ~1u;
        bool nz = present && (l > 0);

        fm[w][l][0] = m0; fm[w][l][1] = m1; fm[w][l][2] = m2; fm[w][l][3] = m3;
        __syncwarp();

        ull p2 = g_p2[w * LBL + l];
        float sv = (float)(double)(p2 >> 22) * INV_S_VAL;
        float ct = (float)(unsigned)(p2 & 0x3FFFFFull);
        float aggl = nz ? sv / fmaxf(ct, 1.f) : 0.f;

        float sq = m0*m0 + m1*m1 + m2*m2 + m3*m3;
        float nrm = (sq > 0.f) ? sqrtf(sq) : 0.f;
        float reg = present ? log1pf(nrm) : 0.f;

        float ds = 0.f, dc = 0.f;
        if (nz) {
            #pragma unroll
            for (int j = 1; j < LBL; j++) {
                if (j != l && ((nzb >> j) & 1u)) {
                    float p0 = m0 - fm[w][j][0];
                    float p1 = m1 - fm[w][j][1];
                    float p2f = m2 - fm[w][j][2];
                    float p3 = m3 - fm[w][j][3];
                    float psq = p0*p0 + p1*p1 + p2f*p2f + p3*p3;
                    float pd = (psq > 0.f) ? sqrtf(psq) : 0.f;
                    float r = fmaxf(3.0f - pd, 0.f);     // 2*DELTA_DIS
                    ds += log1pf(r * r);
                    dc += 1.f;
                }
            }
        }
        for (int o = 16; o; o >>= 1) {
            aggl += __shfl_down_sync(0xffffffffu, aggl, o);
            reg  += __shfl_down_sync(0xffffffffu, reg,  o);
            ds   += __shfl_down_sync(0xffffffffu, ds,   o);
            dc   += __shfl_down_sync(0xffffffffu, dc,   o);
        }
        if (l == 0) {
            float l_agg = aggl / (float)((ni - 1) > 1 ? (ni - 1) : 1);
            float l_reg = reg / (float)(ni > 1 ? ni : 1) * 0.001f;
            float l_dis = (ni > 2) ? ds / fmaxf(dc, 1.f) : 0.f;
            out[w] = (ni <= 1) ? 0.f : (l_agg + l_dis + l_reg);
        }
    }
    __syncthreads();     // all reads done — reset scratch for next graph replay
    if (tid < BMAX * LBL) {
        g_s01[tid] = 0ull;
        g_s23[tid] = 0ull;
        g_cnt1[tid] = 0;
        g_p2[tid]  = 0ull;
    }
    if (tid == 0) { g_bar1 = 0u; g_bar2 = 0u; }
}

extern "C" void kernel_launch(void* const* d_in, const int* in_sizes, int n_in,
                              void* d_out, int out_size) {
    const float* emb  = (const float*)d_in[0];
    const int*   inst = (const int*)  d_in[1];
    const float* ker  = (const float*)d_in[2];
    const float* tmk  = (const float*)d_in[3];
    float* out = (float*)d_out;

    int B = out_size;
    if (B > BMAX) B = BMAX;
    int NPIX = in_sizes[1] / B;
    int NG = NPIX >> 2;

    // B*CPB blocks, guaranteed co-resident by __launch_bounds__(256, 6)
    // (592 blocks = 148 SMs x 4; launch_bounds permits >= 6/SM)
    k_fused<<<B * CPB, 256>>>(emb, inst, ker, tmk, out, NG, NPIX, B);
}

// round 6
// speedup vs baseline: 1.3413x; 1.0684x over previous
#include <cuda_runtime.h>

#define LBL 32
#define BMAX 8
#define CPB 111          // chunks per batch -> grid = 8*111 = 888 = 148*6 (co-resident)
typedef unsigned long long ull;
typedef long long ll;

#define S_EMB 65536.f          // 2^16 fixed-point scale for embedding sums
#define INV_S_EMB (1.f/65536.f)
#define S_VAL 262144.f         // 2^18 scale for log-val sums
#define INV_S_VAL (1.f/262144.f)

// scratch (zeroed at module load; finalize re-zeros for next graph replay)
__device__ ull g_s01[BMAX * LBL];   // packed (sum_e0, sum_e1)
__device__ ull g_s23[BMAX * LBL];   // packed (sum_e2, sum_e3)
__device__ int g_cnt1[BMAX * LBL];  // kernel-region counts
__device__ ull g_p2[BMAX * LBL];    // packed (sum_val<<22) + cnt
__device__ unsigned g_bar1, g_bar2;

__device__ __forceinline__ ull pack2(float a, float b) {
    int ia = __float2int_rn(a * S_EMB);
    int ib = __float2int_rn(b * S_EMB);
    return (ull)(((ll)ib << 32) + (ll)ia);
}
__device__ __forceinline__ void unpack2(ull p, float& a, float& b) {
    ll P = (ll)p;
    int ia = (int)(unsigned)(P & 0xFFFFFFFFll);
    int ib = (int)((P - (ll)ia) >> 32);
    a = (float)ia * INV_S_EMB;
    b = (float)ib * INV_S_EMB;
}

__global__ void __launch_bounds__(256, 6) k_fused(
    const float* __restrict__ emb, const int* __restrict__ inst,
    const float* __restrict__ ker, const float* __restrict__ tmk,
    float* __restrict__ out, int NG, int NPIX, int B)
{
    const int tid   = threadIdx.x;
    const int b     = blockIdx.x % B;
    const int chunk = blockIdx.x / B;
    const int CS    = (NG + CPB - 1) / CPB;
    const int gBeg  = chunk * CS;
    const int gEnd  = (gBeg + CS < NG) ? gBeg + CS : NG;

    __shared__ ull s01[LBL], s23[LBL], sp2[LBL];
    __shared__ int scnt[LBL];
    __shared__ float4 meanv[LBL];
    __shared__ int isLast;

    if (tid < LBL) { s01[tid] = 0ull; s23[tid] = 0ull; sp2[tid] = 0ull; scnt[tid] = 0; }
    __syncthreads();

    const int4*   ip  = (const int4*)  (inst + (size_t)b * NPIX);
    const float4* kp  = (const float4*)(ker  + (size_t)b * NPIX);
    const float4* mp  = (const float4*)(tmk  + (size_t)b * NPIX);
    const float*  ep  = emb + (size_t)b * 4 * NPIX;
    const float4* e0p = (const float4*)(ep);
    const float4* e1p = (const float4*)(ep + NPIX);
    const float4* e2p = (const float4*)(ep + 2 * NPIX);
    const float4* e3p = (const float4*)(ep + 3 * NPIX);

    // ---------------- pass 1: kernel-region per-label counts + sums ----------
    for (int g = gBeg + tid; g < gEnd; g += 256) {
        int4   lb = ip[g];
        float4 kv = kp[g];
        float4 mv = mp[g];
        int l0 = (fminf(kv.x, mv.x) > 0.5f) ? lb.x : 0;
        int l1 = (fminf(kv.y, mv.y) > 0.5f) ? lb.y : 0;
        int l2 = (fminf(kv.z, mv.z) > 0.5f) ? lb.z : 0;
        int l3 = (fminf(kv.w, mv.w) > 0.5f) ? lb.w : 0;
        if ((l0 | l1 | l2 | l3) != 0) {
            float4 e0 = e0p[g], e1 = e1p[g], e2 = e2p[g], e3 = e3p[g];
            if (l0) { atomicAdd(&s01[l0], pack2(e0.x, e1.x)); atomicAdd(&s23[l0], pack2(e2.x, e3.x)); atomicAdd(&scnt[l0], 1); }
            if (l1) { atomicAdd(&s01[l1], pack2(e0.y, e1.y)); atomicAdd(&s23[l1], pack2(e2.y, e3.y)); atomicAdd(&scnt[l1], 1); }
            if (l2) { atomicAdd(&s01[l2], pack2(e0.z, e1.z)); atomicAdd(&s23[l2], pack2(e2.z, e3.z)); atomicAdd(&scnt[l2], 1); }
            if (l3) { atomicAdd(&s01[l3], pack2(e0.w, e1.w)); atomicAdd(&s23[l3], pack2(e2.w, e3.w)); atomicAdd(&scnt[l3], 1); }
        }
    }
    int rem = NPIX & 3;
    if (rem && chunk == 0 && tid < rem) {
        int i = NG * 4 + tid;
        const int*   ips = inst + (size_t)b * NPIX;
        const float* kps = ker  + (size_t)b * NPIX;
        const float* mps = tmk  + (size_t)b * NPIX;
        int l = (fminf(kps[i], mps[i]) > 0.5f) ? ips[i] : 0;
        if (l) {
            atomicAdd(&s01[l], pack2(ep[i], ep[i + NPIX]));
            atomicAdd(&s23[l], pack2(ep[i + 2 * NPIX], ep[i + 3 * NPIX]));
            atomicAdd(&scnt[l], 1);
        }
    }
    __syncthreads();
    if (tid >= 1 && tid < LBL && scnt[tid]) {
        atomicAdd(&g_s01[b * LBL + tid], s01[tid]);
        atomicAdd(&g_s23[b * LBL + tid], s23[tid]);
        atomicAdd(&g_cnt1[b * LBL + tid], scnt[tid]);
    }
    __threadfence();
    __syncthreads();

    // ---------------- device-wide barrier (all 888 blocks co-resident) --------
    if (tid == 0) {
        atomicAdd(&g_bar1, 1u);
        volatile unsigned* vb = &g_bar1;
        while (*vb < (unsigned)gridDim.x) __nanosleep(100);
    }
    __syncthreads();
    __threadfence();

    // ---------------- pass 2: distances to per-label means --------------------
    if (tid < LBL) {
        float m0 = 0.f, m1 = 0.f, m2 = 0.f, m3 = 0.f;
        if (tid > 0) {
            float inv = 1.f / fmaxf((float)g_cnt1[b * LBL + tid], 1.f);
            float a0, a1, a2, a3;
            unpack2(g_s01[b * LBL + tid], a0, a1);
            unpack2(g_s23[b * LBL + tid], a2, a3);
            m0 = a0 * inv; m1 = a1 * inv; m2 = a2 * inv; m3 = a3 * inv;
        }
        meanv[tid] = make_float4(m0, m1, m2, m3);
    }
    __syncthreads();

    for (int g = gBeg + tid; g < gEnd; g += 256) {
        int4   lb = ip[g];
        float4 mv = mp[g];
        int l0 = (mv.x > 0.5f) ? lb.x : 0;
        int l1 = (mv.y > 0.5f) ? lb.y : 0;
        int l2 = (mv.z > 0.5f) ? lb.z : 0;
        int l3 = (mv.w > 0.5f) ? lb.w : 0;
        if ((l0 | l1 | l2 | l3) != 0) {
            float4 e0 = e0p[g], e1 = e1p[g], e2 = e2p[g], e3 = e3p[g];
            #define PAN_PIX(L, X)                                              \
                if (L) {                                                       \
                    float4 m = meanv[L];                                       \
                    float d0 = e0.X - m.x, d1 = e1.X - m.y;                    \
                    float d2 = e2.X - m.z, d3 = e3.X - m.w;                    \
                    float sq = fmaf(d0,d0, fmaf(d1,d1, fmaf(d2,d2, d3*d3)));   \
                    float dist = (sq > 0.f) ? sq * rsqrtf(sq) : 0.f;           \
                    float r = fmaxf(dist - 0.5f, 0.f);                         \
                    float val = __logf(fmaf(r, r, 1.f));                       \
                    unsigned vf = (unsigned)__float2int_rn(val * S_VAL);       \
                    atomicAdd(&sp2[L], ((ull)vf << 22) + 1ull);                \
                }
            PAN_PIX(l0, x) PAN_PIX(l1, y) PAN_PIX(l2, z) PAN_PIX(l3, w)
            #undef PAN_PIX
        }
    }
    if (rem && chunk == 0 && tid < rem) {
        int i = NG * 4 + tid;
        const int*   ips = inst + (size_t)b * NPIX;
        const float* mps = tmk  + (size_t)b * NPIX;
        int l = (mps[i] > 0.5f) ? ips[i] : 0;
        if (l) {
            float4 m = meanv[l];
            float d0 = ep[i] - m.x, d1 = ep[i+NPIX] - m.y;
            float d2 = ep[i+2*NPIX] - m.z, d3 = ep[i+3*NPIX] - m.w;
            float sq = fmaf(d0,d0, fmaf(d1,d1, fmaf(d2,d2, d3*d3)));
            float dist = (sq > 0.f) ? sq * rsqrtf(sq) : 0.f;
            float r = fmaxf(dist - 0.5f, 0.f);
            unsigned vf = (unsigned)__float2int_rn(__logf(fmaf(r, r, 1.f)) * S_VAL);
            atomicAdd(&sp2[l], ((ull)vf << 22) + 1ull);
        }
    }
    __syncthreads();
    if (tid >= 1 && tid < LBL && sp2[tid]) atomicAdd(&g_p2[b * LBL + tid], sp2[tid]);
    __threadfence();
    __syncthreads();
    if (tid == 0)
        isLast = (atomicAdd(&g_bar2, 1u) == (unsigned)gridDim.x - 1u);
    __syncthreads();
    if (!isLast) return;

    // ---------------- finalize: warp w handles batch w -------------------------
    __threadfence();
    __shared__ float fm[BMAX][LBL][4];
    const int w = tid >> 5;
    const int l = tid & 31;

    if (w < B) {
        int   ci = g_cnt1[w * LBL + l];           // 0 for l==0 (never accumulated)
        float c  = (float)ci;
        float m0 = 0.f, m1 = 0.f, m2 = 0.f, m3 = 0.f;
        if (l > 0 && ci > 0) {
            float inv = 1.f / c;
            float a0, a1, a2, a3;
            unpack2(g_s01[w * LBL + l], a0, a1);
            unpack2(g_s23[w * LBL + l], a2, a3);
            m0 = a0 * inv; m1 = a1 * inv; m2 = a2 * inv; m3 = a3 * inv;
        }
        // recover label-0 count: NPIX - sum of active counts
        float csum = (l > 0) ? c : 0.f;
        for (int o = 16; o; o >>= 1) csum += __shfl_xor_sync(0xffffffffu, csum, o);
        if (l == 0) c = (float)NPIX - csum;

        bool present = (c > 0.f);
        unsigned pb = __ballot_sync(0xffffffffu, present);
        int ni = __popc(pb);
        unsigned nzb = pb & ~1u;
        bool nz = present && (l > 0);

        fm[w][l][0] = m0; fm[w][l][1] = m1; fm[w][l][2] = m2; fm[w][l][3] = m3;
        __syncwarp();

        ull p2 = g_p2[w * LBL + l];
        float sv = (float)(double)(p2 >> 22) * INV_S_VAL;
        float ct = (float)(unsigned)(p2 & 0x3FFFFFull);
        float aggl = nz ? sv / fmaxf(ct, 1.f) : 0.f;

        float sq = m0*m0 + m1*m1 + m2*m2 + m3*m3;
        float nrm = (sq > 0.f) ? sqrtf(sq) : 0.f;
        float reg = present ? log1pf(nrm) : 0.f;

        float ds = 0.f, dc = 0.f;
        if (nz) {
            #pragma unroll
            for (int j = 1; j < LBL; j++) {
                if (j != l && ((nzb >> j) & 1u)) {
                    float p0 = m0 - fm[w][j][0];
                    float p1 = m1 - fm[w][j][1];
                    float p2f = m2 - fm[w][j][2];
                    float p3 = m3 - fm[w][j][3];
                    float psq = p0*p0 + p1*p1 + p2f*p2f + p3*p3;
                    float pd = (psq > 0.f) ? sqrtf(psq) : 0.f;
                    float r = fmaxf(3.0f - pd, 0.f);     // 2*DELTA_DIS
                    ds += log1pf(r * r);
                    dc += 1.f;
                }
            }
        }
        for (int o = 16; o; o >>= 1) {
            aggl += __shfl_down_sync(0xffffffffu, aggl, o);
            reg  += __shfl_down_sync(0xffffffffu, reg,  o);
            ds   += __shfl_down_sync(0xffffffffu, ds,   o);
            dc   += __shfl_down_sync(0xffffffffu, dc,   o);
        }
        if (l == 0) {
            float l_agg = aggl / (float)((ni - 1) > 1 ? (ni - 1) : 1);
            float l_reg = reg / (float)(ni > 1 ? ni : 1) * 0.001f;
            float l_dis = (ni > 2) ? ds / fmaxf(dc, 1.f) : 0.f;
            out[w] = (ni <= 1) ? 0.f : (l_agg + l_dis + l_reg);
        }
    }
    __syncthreads();     // all reads done — reset scratch for next graph replay
    if (tid < BMAX * LBL) {
        g_s01[tid] = 0ull;
        g_s23[tid] = 0ull;
        g_cnt1[tid] = 0;
        g_p2[tid]  = 0ull;
    }
    if (tid == 0) { g_bar1 = 0u; g_bar2 = 0u; }
}

extern "C" void kernel_launch(void* const* d_in, const int* in_sizes, int n_in,
                              void* d_out, int out_size) {
    const float* emb  = (const float*)d_in[0];
    const int*   inst = (const int*)  d_in[1];
    const float* ker  = (const float*)d_in[2];
    const float* tmk  = (const float*)d_in[3];
    float* out = (float*)d_out;

    int B = out_size;
    if (B > BMAX) B = BMAX;
    int NPIX = in_sizes[1] / B;
    int NG = NPIX >> 2;

    // 888 blocks = 148 SMs x 6, co-residency guaranteed by __launch_bounds__(256, 6)
    k_fused<<<B * CPB, 256>>>(emb, inst, ker, tmk, out, NG, NPIX, B);
}